// round 13
// baseline (speedup 1.0000x reference)
#include <cuda_runtime.h>
#include <cuda_bf16.h>
#include <cstdint>

#define B      512
#define DIM    128
#define MARGIN 0.2f
#define EPSF   1e-6f
#define BIGF   1e30f
#define SENTTH 1e29f
#define FULLM  0xffffffffu

#define LDU 132          // u row stride (floats)
#define LDC 36           // chunk-buffer row stride (floats): 32 dims + 4 pad
#define LDD 516          // D slab row stride (floats)
#define NT  512          // threads per block
#define NCH 4            // d-chunks of 32 dims

// Accumulators (allocation-free rule). Statics init to zero; the last block
// resets them after use, so every graph replay starts from zero.
__device__ double g_num = 0.0;
__device__ unsigned long long g_den = 0ull;
__device__ unsigned int g_done = 0u;

static __device__ __forceinline__ unsigned smem_u32(const void* p) {
    return (unsigned)__cvta_generic_to_shared(p);
}

#define FMA2(acc, a, b) \
    asm volatile("fma.rn.f32x2 %0, %1, %2, %0;" : "+l"(acc) : "l"(a), "l"(b))
#define LDS_V2B64(lo, hi, addr) \
    asm volatile("ld.shared.v2.b64 {%0, %1}, [%2];" : "=l"(lo), "=l"(hi) : "r"(addr))

static __device__ __forceinline__ float hadd_f32x2(uint64_t p) {
    float lo, hi;
    asm volatile("mov.b64 {%0, %1}, %2;" : "=f"(lo), "=f"(hi) : "l"(p));
    return lo + hi;
}

// ---------------------------------------------------------------------------
// ONE fused kernel, 512 threads. Block b = anchor rows [4b, 4b+4).
// Phase A: thread tid owns j-column tid for all 4 anchors. Loop over 4
//   d-chunks of 32 dims, double-buffered cp.async (chunk c+2 in flight while
//   chunk c computes). No cross-thread combine: each thread finishes its own
//   4 dots + norm and writes D directly.
// Phase B (warps 0-3): register-resident bitonic sort per row (R6-verified),
//   LSB tag + closed-form prefix, single atomic finalize.
// ---------------------------------------------------------------------------
__global__ __launch_bounds__(NT) void fused_kernel(const float* __restrict__ F,
                                                   const int* __restrict__ mask,
                                                   float* __restrict__ out) {
    extern __shared__ float sm[];
    float* u_s  = sm;                          //   4 * 132
    float* Fc_s = u_s + 4 * LDU;               // 2 * 512 * 36 (chunk buffers)
    float* D_s  = Fc_s + 2 * B * LDC;          //   4 * 516
    float* s_ni = D_s + 4 * LDD;               //   4
    float* s_bs = s_ni + 4;                    //   4
    unsigned long long* s_bd = (unsigned long long*)(s_bs + 4);   // 4

    const int tid  = threadIdx.x;
    const int lane = tid & 31;
    const int warp = tid >> 5;
    const int i0   = blockIdx.x * 4;

    // ---- prefetch mask row for my sort row (warps 0-3) ----------------------
    int4 m4p[4];
    if (warp < 4) {
        const int4* Mrow = (const int4*)(mask + (i0 + warp) * B);
#pragma unroll
        for (int qq = 0; qq < 4; qq++) m4p[qq] = Mrow[lane * 4 + qq];
    }

    // ---- stage u = f(anchor rows) + eps (1 element per thread) --------------
    {
        const int r = tid >> 7, d = tid & 127;
        u_s[r * LDU + d] = F[(i0 + r) * DIM + d] + EPSF;
    }

    // ---- cp.async staging: chunk c -> buffer c&1 -----------------------------
    // granule g_global = tid + k*512 (k=0..7); row = g>>3, sub = g&7 (16B each)
    // src: F + row*128 + c*32 floats + sub*4 floats ; dst stride LDC floats.
#define CP_CHUNK(C)                                                            \
    {                                                                          \
        const int buf = (C) & 1;                                               \
        _Pragma("unroll")                                                      \
        for (int k = 0; k < 8; k++) {                                          \
            const int g   = tid + (k << 9);                                    \
            const int row = g >> 3;                                            \
            const int sub = g & 7;                                             \
            const unsigned dst =                                               \
                smem_u32(&Fc_s[buf * B * LDC + row * LDC + sub * 4]);          \
            const float* src = F + row * DIM + (C) * 32 + sub * 4;             \
            asm volatile("cp.async.cg.shared.global [%0], [%1], 16;"           \
                         :: "r"(dst), "l"(src));                               \
        }                                                                      \
        asm volatile("cp.async.commit_group;");                                \
    }

    CP_CHUNK(0)
    CP_CHUNK(1)

    __syncthreads();   // u_s visible

    // ---- |u_i|^2 (warps 0-3; warp w -> row w) --------------------------------
    if (warp < 4) {
        float s = 0.f;
#pragma unroll
        for (int qq = 0; qq < 4; qq++) {
            const float x = u_s[warp * LDU + lane + 32 * qq];
            s = fmaf(x, x, s);
        }
#pragma unroll
        for (int off = 16; off; off >>= 1) s += __shfl_down_sync(FULLM, s, off);
        if (lane == 0) s_ni[warp] = s;
    }

    // ---- Phase A: 4 d-chunks, double-buffered --------------------------------
    uint64_t A0 = 0ull, A1 = 0ull, A2 = 0ull, A3 = 0ull, NF2 = 0ull;
    const unsigned ub  = smem_u32(u_s);
    const unsigned fcb = smem_u32(Fc_s);

#pragma unroll
    for (int c = 0; c < NCH; c++) {
        if (c < NCH - 1) asm volatile("cp.async.wait_group 1;");
        else             asm volatile("cp.async.wait_group 0;");
        __syncthreads();   // chunk c visible to all threads

        const unsigned fb = fcb + ((unsigned)(c & 1) * B * LDC + tid * LDC) * 4u;
        const unsigned uc = ub + c * 128u;   // c*32 floats
#pragma unroll
        for (int dq = 0; dq < 8; dq++) {
            uint64_t f0, f1, x0, x1;
            LDS_V2B64(f0, f1, fb + 16 * dq);
            FMA2(NF2, f0, f0);
            FMA2(NF2, f1, f1);
            LDS_V2B64(x0, x1, uc + 0 * (LDU * 4) + 16 * dq);
            FMA2(A0, x0, f0);
            FMA2(A0, x1, f1);
            LDS_V2B64(x0, x1, uc + 1 * (LDU * 4) + 16 * dq);
            FMA2(A1, x0, f0);
            FMA2(A1, x1, f1);
            LDS_V2B64(x0, x1, uc + 2 * (LDU * 4) + 16 * dq);
            FMA2(A2, x0, f0);
            FMA2(A2, x1, f1);
            LDS_V2B64(x0, x1, uc + 3 * (LDU * 4) + 16 * dq);
            FMA2(A3, x0, f0);
            FMA2(A3, x1, f1);
        }
        __syncthreads();   // all threads done reading buffer c&1
        if (c + 2 < NCH) CP_CHUNK(c + 2)
    }

    // ---- epilogue: D row slab (no combine — thread owns its column) ----------
    {
        const float a0 = hadd_f32x2(A0);
        const float a1 = hadd_f32x2(A1);
        const float a2 = hadd_f32x2(A2);
        const float a3 = hadd_f32x2(A3);
        const float nf = hadd_f32x2(NF2);
        D_s[0 * LDD + tid] = sqrtf(fmaxf(s_ni[0] + nf - 2.f * a0, 0.f));
        D_s[1 * LDD + tid] = sqrtf(fmaxf(s_ni[1] + nf - 2.f * a1, 0.f));
        D_s[2 * LDD + tid] = sqrtf(fmaxf(s_ni[2] + nf - 2.f * a2, 0.f));
        D_s[3 * LDD + tid] = sqrtf(fmaxf(s_ni[3] + nf - 2.f * a3, 0.f));
    }
    __syncthreads();   // D_s complete

    // =========================================================================
    // Phase B (warps 0-3): register-resident sort of row i0+warp (R6-verified).
    // Element e = lane*16 + r. LSB tag: pos=(d+margin)|1, neg=d&~1,
    // excluded diagonal = BIGF (value-guarded out of float sums).
    // =========================================================================
    if (warp < 4) {
        const int i = i0 + warp;
        float v[16];
        int npos = 0, nneg = 0;

#pragma unroll
        for (int qq = 0; qq < 4; qq++) {
            const float4 d4 = *(const float4*)&D_s[warp * LDD + lane * 16 + 4 * qq];
            const float dv[4] = {d4.x, d4.y, d4.z, d4.w};
            const int   mv[4] = {m4p[qq].x, m4p[qq].y, m4p[qq].z, m4p[qq].w};
#pragma unroll
            for (int t = 0; t < 4; t++) {
                const int j = lane * 16 + qq * 4 + t;
                unsigned kb;
                if (mv[t] != 0) {
                    kb = __float_as_uint(dv[t] + MARGIN) | 1u;
                    npos++;
                } else if (j == i) {
                    kb = __float_as_uint(BIGF) & ~1u;
                } else {
                    kb = __float_as_uint(dv[t]) & ~1u;
                    nneg++;
                }
                v[qq * 4 + t] = __uint_as_float(kb);
            }
        }
        const int np = __reduce_add_sync(FULLM, npos);
        const int nn = __reduce_add_sync(FULLM, nneg);

        // bitonic sort of 512 keys, ascending (register + shfl only)
#pragma unroll
        for (int k = 2; k <= 512; k <<= 1) {
            const bool asc_lane_valid = (k >= 16);
            const bool asc_l = ((lane & (k >> 4)) == 0);
#pragma unroll
            for (int j = k >> 1; j >= 1; j >>= 1) {
                if (j >= 16) {
                    const int jl2 = j >> 4;
                    const bool keep_min = (((lane & jl2) == 0) == asc_l);
#pragma unroll
                    for (int r = 0; r < 16; r++) {
                        const float pv = __shfl_xor_sync(FULLM, v[r], jl2);
                        v[r] = keep_min ? fminf(v[r], pv) : fmaxf(v[r], pv);
                    }
                } else {
#pragma unroll
                    for (int r = 0; r < 16; r++) {
                        if ((r & j) == 0) {
                            const int r2 = r | j;
                            const bool asc = asc_lane_valid ? asc_l : ((r & k) == 0);
                            const float a = v[r], bb = v[r2];
                            const float lo = fminf(a, bb), hi = fmaxf(a, bb);
                            v[r]  = asc ? lo : hi;
                            v[r2] = asc ? hi : lo;
                        }
                    }
                }
            }
        }

        // pass 1: per-lane negative (sum, count), sentinel value-guarded
        float runs = 0.f;
        int   runc = 0;
#pragma unroll
        for (int r = 0; r < 16; r++) {
            const bool isneg = ((__float_as_uint(v[r]) & 1u) == 0) && (v[r] < SENTTH);
            if (isneg) { runs += v[r]; runc++; }
        }
        float ls = runs;
        int   lc = runc;
#pragma unroll
        for (int off = 1; off < 32; off <<= 1) {
            const float y = __shfl_up_sync(FULLM, ls, off);
            const int   z = __shfl_up_sync(FULLM, lc, off);
            if (lane >= off) { ls += y; lc += z; }
        }
        float rs = ls - runs;
        int   rc = lc - runc;

        // pass 2: positive contributions
        float local = 0.f;
#pragma unroll
        for (int r = 0; r < 16; r++) {
            const bool ispos = (__float_as_uint(v[r]) & 1u) != 0;
            if (ispos) {
                local += (float)rc * v[r] - rs;
            } else if (v[r] < SENTTH) {
                rs += v[r];
                rc++;
            }
        }

#pragma unroll
        for (int off = 16; off; off >>= 1)
            local += __shfl_down_sync(FULLM, local, off);

        if (lane == 0) {
            s_bs[warp] = local;
            s_bd[warp] = (unsigned long long)np * (unsigned long long)nn;
        }
    }
    __syncthreads();

    if (tid == 0) {
        const float s = s_bs[0] + s_bs[1] + s_bs[2] + s_bs[3];
        const unsigned long long d = s_bd[0] + s_bd[1] + s_bd[2] + s_bd[3];
        atomicAdd(&g_num, (double)s);
        atomicAdd(&g_den, d);
        __threadfence();
        const unsigned int ticket = atomicAdd(&g_done, 1u);
        if (ticket == gridDim.x - 1) {
            const double num = atomicAdd(&g_num, 0.0);
            const unsigned long long den = atomicAdd(&g_den, 0ull);
            out[0] = (den > 0ull) ? (float)(num / (double)den) : 0.0f;
            g_num  = 0.0;
            g_den  = 0ull;
            __threadfence();
            g_done = 0u;
        }
    }
}

// ---------------------------------------------------------------------------
extern "C" void kernel_launch(void* const* d_in, const int* in_sizes, int n_in,
                              void* d_out, int out_size) {
    const float* features = (const float*)d_in[0];   // [512,128] f32
    const int*   mask     = (const int*)d_in[1];     // [512,512] i32
    float* out = (float*)d_out;

    const int smem_bytes =
        (4 * LDU + 2 * B * LDC + 4 * LDD + 4 + 4) * (int)sizeof(float)
        + 4 * (int)sizeof(unsigned long long);
    static bool attr_set = false;
    if (!attr_set) {
        cudaFuncSetAttribute(fused_kernel, cudaFuncAttributeMaxDynamicSharedMemorySize,
                             smem_bytes);
        attr_set = true;
    }

    fused_kernel<<<B / 4, NT, smem_bytes>>>(features, mask, out);
}